// round 7
// baseline (speedup 1.0000x reference)
#include <cuda_runtime.h>
#include <stdint.h>

// FullMultiEmbedding fused single-pass:
//   out[b, e, :] = weight[e, :] * psw[i]  if e == input_[i] for some i in bag b
//                = 0                       otherwise
// Output [B, NUM_EMB, D] fp32 (D=64), 655 MB -> purely HBM-write-bound.
//
// Inputs (JAX x64 disabled -> "int64" arrays are int32 on the wire):
//   d_in[0] input_             int32   [L]   (12800)
//   d_in[1] offsets            int32   [B]   (256)
//   d_in[2] per_sample_weights float32 [L]
//   d_in[3] weight             float32 [NUM_EMB, 64] (10000 x 64)
//
// Fast path: each bag's indices form a consecutive run (start+j) % num_emb.
// This is VERIFIED per block; membership then costs 2 integer ops per row.
// Fallback (arbitrary data): linear scan of the bag's index list in SMEM.

static constexpr int D4      = 16;   // 64 floats = 16 float4 per row
static constexpr int SPLITS  = 18;   // row-slices per bag -> 256*18 = 4608 blocks
static constexpr int THREADS = 256;  // 16 rows x 16 float4-lanes per iteration
static constexpr int CAP     = 2048; // SMEM cache for bag indices (fallback path)

__global__ void __launch_bounds__(THREADS) fused_kernel(
        const int* __restrict__ input_,
        const int* __restrict__ offsets,
        const float* __restrict__ psw,
        const float4* __restrict__ weight,
        float4* __restrict__ out,
        int L, int B, int num_emb, int rows_per_slice) {
    __shared__ int   e_list[CAP];
    __shared__ float w_list[CAP];
    __shared__ int   s_consec;

    const int bag   = blockIdx.x / SPLITS;
    const int slice = blockIdx.x % SPLITS;

    const int off = offsets[bag];
    const int end = (bag + 1 < B) ? offsets[bag + 1] : L;
    const int len = end - off;
    const int start = (len > 0) ? input_[off] : 0;
    const bool cache = (len <= CAP);

    if (threadIdx.x == 0) s_consec = 1;
    __syncthreads();
    for (int j = threadIdx.x; j < len; j += THREADS) {
        int e = input_[off + j];
        if (cache) { e_list[j] = e; w_list[j] = psw[off + j]; }
        int expect = start + j;
        if (expect >= num_emb) expect -= num_emb;
        if (e != expect) s_consec = 0;   // any-thread clear; barrier below
    }
    __syncthreads();
    const bool consec = (s_consec != 0) && cache;

    // ---- stream this slice's rows ----
    const int e0 = slice * rows_per_slice;
    const int e1 = min(e0 + rows_per_slice, num_emb);
    const int d4 = threadIdx.x & 15;   // float4 lane in row
    const int r  = threadIdx.x >> 4;   // row within iteration (0..15)

    int e = e0 + r;
    if (e >= e1) return;

    // distance from run start, kept in [0, num_emb)
    int d = e - start;
    if (d < 0) d += num_emb;

    // 32-bit float4 indexing (max ~41M < 2^31)
    float4* p = out + ((unsigned)(bag * num_emb + e) * D4 + d4);
    const float4 z = make_float4(0.f, 0.f, 0.f, 0.f);

    if (consec) {
        #pragma unroll 4
        for (; e < e1; e += 16) {
            if (d < len) {
                // rare path: ~50 rows/bag
                float w = w_list[d];
                float4 v = weight[(unsigned)e * D4 + d4];
                v.x *= w; v.y *= w; v.z *= w; v.w *= w;
                *p = v;
            } else {
                *p = z;
            }
            d += 16; if (d >= num_emb) d -= num_emb;
            p += 16 * D4;
        }
    } else {
        // general fallback: scan the bag's indices (last match wins)
        for (; e < e1; e += 16) {
            float w = 0.f; bool hit = false;
            if (cache) {
                for (int j = 0; j < len; j++)
                    if (e_list[j] == e) { w = w_list[j]; hit = true; }
            } else {
                for (int j = 0; j < len; j++)
                    if (input_[off + j] == e) { w = psw[off + j]; hit = true; }
            }
            float4 v = z;
            if (hit) {
                v = weight[(unsigned)e * D4 + d4];
                v.x *= w; v.y *= w; v.z *= w; v.w *= w;
            }
            *p = v;
            p += 16 * D4;
        }
    }
}

extern "C" void kernel_launch(void* const* d_in, const int* in_sizes, int n_in,
                              void* d_out, int out_size) {
    const int*   input_  = (const int*)d_in[0];
    const int*   offsets = (const int*)d_in[1];
    const float* psw     = (const float*)d_in[2];
    const float* weight  = (const float*)d_in[3];
    float* out = (float*)d_out;

    const int L = in_sizes[0];
    const int B = in_sizes[1];
    const int num_emb = in_sizes[3] / 64;

    const int rows_per_slice = (num_emb + SPLITS - 1) / SPLITS;
    const int blocks = B * SPLITS;

    fused_kernel<<<blocks, THREADS>>>(input_, offsets, psw,
                                      (const float4*)weight,
                                      (float4*)out,
                                      L, B, num_emb, rows_per_slice);
}

// round 8
// speedup vs baseline: 1.0146x; 1.0146x over previous
#include <cuda_runtime.h>
#include <stdint.h>

// FullMultiEmbedding fused single-pass (interval form):
//   out[b, e, :] = weight[e, :] * psw[i]  if e == input_[i] for some i in bag b
//                = 0                       otherwise
// Output [B, NUM_EMB, 64] fp32, 655 MB -> HBM-write-bound.
//
// Inputs (JAX x64 disabled -> "int64" arrays are int32 on the wire):
//   d_in[0] input_             int32   [L]   (12800)
//   d_in[1] offsets            int32   [B]   (256)
//   d_in[2] per_sample_weights float32 [L]
//   d_in[3] weight             float32 [NUM_EMB, 64]
//
// Fast path: bag indices form a consecutive run (start+j) % N (verified per
// block). Hit rows are then <=2 contiguous intervals; zero regions stream as a
// pure memset loop. Fallback: per-row scan of the bag's index list.

static constexpr int D4      = 16;   // 64 floats = 16 float4 per row
static constexpr int SPLITS  = 18;   // 256 bags * 18 = 4608 blocks
static constexpr int THREADS = 256;
static constexpr int CAP     = 2048;

__device__ __forceinline__ void zero_rows(float4* __restrict__ bag_base,
                                          int lo, int hi) {
    int n4 = (hi - lo) << 4;
    float4* p = bag_base + ((unsigned)lo << 4);
    const float4 z = make_float4(0.f, 0.f, 0.f, 0.f);
    #pragma unroll 8
    for (int i = threadIdx.x; i < n4; i += THREADS) p[i] = z;
}

__global__ void __launch_bounds__(THREADS) fused_kernel(
        const int* __restrict__ input_,
        const int* __restrict__ offsets,
        const float* __restrict__ psw,
        const float4* __restrict__ weight,
        float4* __restrict__ out,
        int L, int B, int num_emb, int rows_per_slice) {
    __shared__ int   e_list[CAP];
    __shared__ float w_list[CAP];
    __shared__ int   s_consec;

    const int bag   = blockIdx.x / SPLITS;
    const int slice = blockIdx.x % SPLITS;

    const int off = offsets[bag];
    const int end = (bag + 1 < B) ? offsets[bag + 1] : L;
    const int len = end - off;
    const int start = (len > 0) ? input_[off] : 0;
    const bool cache = (len <= CAP);

    if (threadIdx.x == 0) s_consec = 1;
    __syncthreads();
    for (int j = threadIdx.x; j < len; j += THREADS) {
        int e = input_[off + j];
        if (cache) { e_list[j] = e; w_list[j] = psw[off + j]; }
        int expect = start + j;
        if (expect >= num_emb) expect -= num_emb;
        if (e != expect) s_consec = 0;
    }
    __syncthreads();
    const bool consec = (s_consec != 0) && cache && (len <= num_emb);

    const int e0 = slice * rows_per_slice;
    const int e1 = min(e0 + rows_per_slice, num_emb);
    if (e0 >= e1) return;

    float4* bag_base = out + (unsigned)(bag * num_emb) * D4;

    if (consec) {
        // Hit band = [start, start+len) mod N  ->  <=2 row intervals:
        //   wrap part  [0, wrap_end)            (d = row - start + N)
        //   main part  [start, band_end1)       (d = row - start)
        const int band_end1 = min(start + len, num_emb);
        const int wrap_end  = start + len - num_emb;  // may be <= 0

        // clamp to [e0, e1), monotone: e0 <= Lb <= Ha <= Hb <= e1
        int Lb = min(e1, max(wrap_end, e0));          // end of wrap-hit segment
        int Ha = min(e1, max(start, Lb));             // start of main-hit segment
        int Hb = min(e1, max(band_end1, Ha));         // end of main-hit segment

        // 1) wrap-hit rows [e0, Lb)
        {
            int n4 = (Lb - e0) << 4;
            int dbase = e0 - start + num_emb;
            for (int i = threadIdx.x; i < n4; i += THREADS) {
                int row = e0 + (i >> 4), lane = i & 15;
                float w = w_list[dbase + (i >> 4)];
                float4 v = weight[(unsigned)row * D4 + lane];
                v.x *= w; v.y *= w; v.z *= w; v.w *= w;
                bag_base[((unsigned)row << 4) + lane] = v;
            }
        }
        // 2) zeros [Lb, Ha)
        zero_rows(bag_base, Lb, Ha);
        // 3) main-hit rows [Ha, Hb)
        {
            int n4 = (Hb - Ha) << 4;
            int dbase = Ha - start;
            for (int i = threadIdx.x; i < n4; i += THREADS) {
                int row = Ha + (i >> 4), lane = i & 15;
                float w = w_list[dbase + (i >> 4)];
                float4 v = weight[(unsigned)row * D4 + lane];
                v.x *= w; v.y *= w; v.z *= w; v.w *= w;
                bag_base[((unsigned)row << 4) + lane] = v;
            }
        }
        // 4) zeros [Hb, e1)
        zero_rows(bag_base, Hb, e1);
    } else {
        // general fallback: per-row scan (last match wins)
        const int d4 = threadIdx.x & 15;
        const int r  = threadIdx.x >> 4;
        const float4 z = make_float4(0.f, 0.f, 0.f, 0.f);
        for (int e = e0 + r; e < e1; e += 16) {
            float w = 0.f; bool hit = false;
            if (cache) {
                for (int j = 0; j < len; j++)
                    if (e_list[j] == e) { w = w_list[j]; hit = true; }
            } else {
                for (int j = 0; j < len; j++)
                    if (input_[off + j] == e) { w = psw[off + j]; hit = true; }
            }
            float4 v = z;
            if (hit) {
                v = weight[(unsigned)e * D4 + d4];
                v.x *= w; v.y *= w; v.z *= w; v.w *= w;
            }
            bag_base[((unsigned)e << 4) + d4] = v;
        }
    }
}

extern "C" void kernel_launch(void* const* d_in, const int* in_sizes, int n_in,
                              void* d_out, int out_size) {
    const int*   input_  = (const int*)d_in[0];
    const int*   offsets = (const int*)d_in[1];
    const float* psw     = (const float*)d_in[2];
    const float* weight  = (const float*)d_in[3];
    float* out = (float*)d_out;

    const int L = in_sizes[0];
    const int B = in_sizes[1];
    const int num_emb = in_sizes[3] / 64;

    const int rows_per_slice = (num_emb + SPLITS - 1) / SPLITS;
    const int blocks = B * SPLITS;

    fused_kernel<<<blocks, THREADS>>>(input_, offsets, psw,
                                      (const float4*)weight,
                                      (float4*)out,
                                      L, B, num_emb, rows_per_slice);
}